// round 15
// baseline (speedup 1.0000x reference)
#include <cuda_runtime.h>
#include <cstdint>

// Problem constants
#define Lc     2048
#define Bc     2
#define Hc     32
#define Pc     64
#define Nc     128
#define DPROJ  4384
#define DCONVC 2304
#define DINNER 2048
#define QC     64            // chunk size
#define NCH    (Lc / QC)     // 32 chunks

// ---------------- scratch (static device globals) ---------------------------
__device__ __align__(16) float g_xp [(size_t)Bc * Hc * Lc * 64];       // x~ [bh][t][64]
__device__ __align__(16) float g_gd [(size_t)Bc * Hc * 4 * Lc * 32];   // (gate,Dx) pairs
__device__ __align__(16) float g_B  [(size_t)Bc * Lc * Nc];
__device__ __align__(16) float g_C  [(size_t)Bc * Lc * Nc];
__device__ __align__(16) float g_l  [(size_t)Bc * Hc * Lc];            // l = dt*A
__device__ __align__(16) float g_dAs[(size_t)Bc * Hc * Lc];            // dA scalar
__device__ __align__(16) float g_CB [(size_t)Bc * NCH * QC * QC];      // [b][c][t][i]
__device__ __align__(16) float g_G  [(size_t)Bc * Hc * NCH * Nc * Pc]; // [bhc][n][p]
__device__ __align__(16) float g_stT[(size_t)Bc * Hc * NCH * Nc * Pc]; // [bhc][n][p]
__device__ __align__(16) float g_E  [(size_t)Bc * Hc * NCH];           // chunk decay

// ---------------- helpers ----------------------------------------------------
__device__ __forceinline__ uint64_t pk2(float lo, float hi) {
    uint64_t r; asm("mov.b64 %0, {%1,%2};" : "=l"(r) : "f"(lo), "f"(hi)); return r;
}
__device__ __forceinline__ void unpk2(uint64_t v, float& lo, float& hi) {
    asm("mov.b64 {%0,%1}, %2;" : "=f"(lo), "=f"(hi) : "l"(v));
}
__device__ __forceinline__ uint64_t f2fma(uint64_t a, uint64_t b, uint64_t c) {
    uint64_t d; asm("fma.rn.f32x2 %0, %1, %2, %3;" : "=l"(d) : "l"(a), "l"(b), "l"(c)); return d;
}
__device__ __forceinline__ void cpa16(void* sm, const void* gm) {
    unsigned sa = (unsigned)__cvta_generic_to_shared(sm);
    asm volatile("cp.async.cg.shared.global [%0], [%1], 16;" :: "r"(sa), "l"(gm));
}
__device__ __forceinline__ float fast_silu(float v) {
    return v * (1.f / (1.f + __expf(-v)));
}

// ---------------- pre-pass ---------------------------------------------------
__global__ void prepass_kernel(const float* __restrict__ zx,
                               const float* __restrict__ cw,
                               const float* __restrict__ cb,
                               const float* __restrict__ dt_bias,
                               const float* __restrict__ a_log,
                               const float* __restrict__ d_param,
                               const float* __restrict__ dt_scale) {
    int bt  = blockIdx.x;            // b*L + t
    int b   = bt >> 11;
    int t   = bt & (Lc - 1);
    int idx = blockIdx.y * 256 + threadIdx.x;
    if (idx >= DCONVC + Hc) return;

    if (idx < DCONVC) {
        int cc = idx;
        int col = DINNER + cc;
        float acc = cb[cc];
        const float* w = cw + cc * 4;
        #pragma unroll
        for (int i = 0; i < 4; ++i) {
            int l2 = t - 3 + i;
            if (l2 >= 0) acc += w[i] * zx[((size_t)(b * Lc + l2)) * DPROJ + col];
        }
        float v = fast_silu(acc);
        if (cc < DINNER) {
            int h = cc >> 6, p = cc & 63;
            float draw = zx[(size_t)bt * DPROJ + (DPROJ - Hc) + h] * dt_scale[h] + dt_bias[h];
            float dt = (draw > 20.f) ? draw : log1pf(expf(draw));
            dt = fminf(fmaxf(dt, 0.f), 100.f);
            float xt = dt * v;                       // x~ = dt * x
            g_xp[((size_t)(b * Hc + h) * Lc + t) * 64 + p] = xt;
            float z = zx[(size_t)bt * DPROJ + cc];
            size_t o = ((((size_t)(b * Hc + h) * 4 + (p >> 4)) * Lc + t) * 32 + (p & 15) * 2);
            g_gd[o]     = fast_silu(z);              // gate
            g_gd[o + 1] = d_param[h] * v;            // Dh * x
        } else if (cc < DINNER + Nc) {
            g_B[((size_t)(b * Lc + t)) * Nc + (cc - DINNER)] = v;
        } else {
            g_C[((size_t)(b * Lc + t)) * Nc + (cc - DINNER - Nc)] = v;
        }
    } else {
        int h = idx - DCONVC;
        float draw = zx[(size_t)bt * DPROJ + (DPROJ - Hc) + h] * dt_scale[h] + dt_bias[h];
        float dt = (draw > 20.f) ? draw : log1pf(expf(draw));
        dt = fminf(fmaxf(dt, 0.f), 100.f);
        float A  = -expf(a_log[h]);
        float l  = dt * A;
        g_l  [(size_t)(b * Hc + h) * Lc + t] = l;
        g_dAs[(size_t)(b * Hc + h) * Lc + t] = expf(l);
    }
}

// ---------------- CB kernel: CB[t][i] = C_t . B_i per (b,chunk) --------------
__global__ void __launch_bounds__(256)
cb_kernel() {
    const int bc = blockIdx.x;          // b*NCH + c
    const int b  = bc >> 5;
    const int c  = bc & 31;
    const int tid = threadIdx.x;

    __shared__ float sB[QC * 132];

    for (int idx = tid; idx < QC * 32; idx += 256) {
        int row = idx >> 5, sg = idx & 31;
        cpa16(&sB[row * 132 + sg * 4],
              g_B + ((size_t)b * Lc + c * QC + row) * Nc + sg * 4);
    }
    asm volatile("cp.async.commit_group;");
    asm volatile("cp.async.wait_group 0;");
    __syncthreads();

    const int t  = tid >> 2;
    const int ig = tid & 3;
    const float4* c4p = (const float4*)(g_C + ((size_t)b * Lc + c * QC + t) * Nc);
    float acc[16];
    #pragma unroll
    for (int j = 0; j < 16; ++j) acc[j] = 0.f;

    for (int nq = 0; nq < 32; ++nq) {
        float4 cv = __ldg(c4p + nq);
        #pragma unroll
        for (int j = 0; j < 16; ++j) {
            float4 bv = *(const float4*)&sB[(ig * 16 + j) * 132 + nq * 4];
            acc[j] += cv.x * bv.x + cv.y * bv.y + cv.z * bv.z + cv.w * bv.w;
        }
    }
    float* dst = g_CB + ((size_t)bc * QC + t) * QC + ig * 16;
    #pragma unroll
    for (int j = 0; j < 16; ++j) acc[j] = acc[j];   // keep regs live
    #pragma unroll
    for (int j = 0; j < 16; ++j) dst[j] = acc[j];
}

// ---------------- G kernel: G_c[n][p] = sum_i w_i * x~_i[p] * B_i[n] ---------
#define SMEM_G ((64 * 64 + 64 * 128 + 64 + 64) * 4)   // 49664 B

__global__ void __launch_bounds__(256)
g_kernel() {
    extern __shared__ char dyng[];
    float* sX  = (float*)dyng;              // [i][p] 64x64
    float* sWB = sX + 64 * 64;              // [i][n] 64x128
    float* sac = sWB + 64 * 128;            // [64]
    float* sw  = sac + 64;                  // [64]

    const int bid = blockIdx.x;             // bh*NCH + c
    const int c   = bid & 31;
    const int bh  = bid >> 5;
    const int b   = bh >> 5;
    const int tid = threadIdx.x;

    const float* xbase = g_xp + ((size_t)bh * Lc + c * QC) * 64;
    for (int idx = tid; idx < 1024; idx += 256)
        cpa16(&sX[idx * 4], xbase + idx * 4);
    const float* bbase = g_B + ((size_t)b * Lc + c * QC) * Nc;
    for (int idx = tid; idx < 2048; idx += 256)
        cpa16(&sWB[idx * 4], bbase + idx * 4);
    asm volatile("cp.async.commit_group;");

    if (tid < 64) {
        float v = g_l[(size_t)bh * Lc + c * QC + tid];
        #pragma unroll
        for (int off = 1; off < 32; off <<= 1) {
            float r = __shfl_up_sync(0xffffffffu, v, off);
            if ((tid & 31) >= off) v += r;
        }
        sac[tid] = v;
    }
    __syncthreads();
    if (tid >= 32 && tid < 64) sac[tid] += sac[31];
    __syncthreads();
    float actot = sac[63];
    if (tid < 64) sw[tid] = __expf(actot - sac[tid]);
    if (tid == 0) g_E[(size_t)bh * NCH + c] = __expf(actot);
    asm volatile("cp.async.wait_group 0;");
    __syncthreads();

    // scale B rows by suffix decay w
    for (int idx = tid; idx < 2048; idx += 256) {
        int i = idx >> 5;
        float4* pp = (float4*)&sWB[idx * 4];
        float4 v = *pp;
        float w = sw[i];
        v.x *= w; v.y *= w; v.z *= w; v.w *= w;
        *pp = v;
    }
    __syncthreads();

    // GEMM: out rows = n (128), cols = p (64); tile 4n x 8p per thread
    const int n0 = (tid >> 3) * 4;
    const int p0 = (tid & 7) * 8;
    uint64_t acc[4][4];
    #pragma unroll
    for (int j = 0; j < 4; ++j)
        #pragma unroll
        for (int q = 0; q < 4; ++q) acc[j][q] = 0;

    for (int i = 0; i < 64; ++i) {
        ulonglong2 xv0 = *(const ulonglong2*)&sX[i * 64 + p0];      // p0..p0+3
        ulonglong2 xv1 = *(const ulonglong2*)&sX[i * 64 + p0 + 4];  // p0+4..p0+7
        float wb[4];
        *(float4*)wb = *(const float4*)&sWB[i * 128 + n0];
        #pragma unroll
        for (int j = 0; j < 4; ++j) {
            uint64_t m2 = pk2(wb[j], wb[j]);
            acc[j][0] = f2fma(m2, xv0.x, acc[j][0]);
            acc[j][1] = f2fma(m2, xv0.y, acc[j][1]);
            acc[j][2] = f2fma(m2, xv1.x, acc[j][2]);
            acc[j][3] = f2fma(m2, xv1.y, acc[j][3]);
        }
    }
    #pragma unroll
    for (int j = 0; j < 4; ++j) {
        float* dst = g_G + (((size_t)bid) * Nc + n0 + j) * Pc + p0;
        *(ulonglong2*)dst       = *(ulonglong2*)&acc[j][0];
        *(ulonglong2*)(dst + 4) = *(ulonglong2*)&acc[j][2];
    }
}

// ---------------- chain kernel: elementwise-parallel -------------------------
// S[e] <- E_c*S[e] + G_c[e];  grid = Bc*Hc*8 blocks, thread owns one float4.
__global__ void __launch_bounds__(256)
chain_kernel(const float* __restrict__ init_state) {
    const int bh = blockIdx.x >> 3;
    const int sl = blockIdx.x & 7;
    const int e4 = sl * 256 + threadIdx.x;     // float4 index in [0, 2048)
    const int n  = e4 >> 4;
    const int p0 = (e4 & 15) * 4;

    // init: gather from [p][n] layout
    const float* ist = init_state + (size_t)bh * Pc * Nc;
    float4 S;
    S.x = ist[(size_t)(p0 + 0) * Nc + n];
    S.y = ist[(size_t)(p0 + 1) * Nc + n];
    S.z = ist[(size_t)(p0 + 2) * Nc + n];
    S.w = ist[(size_t)(p0 + 3) * Nc + n];

    const float* Ep = g_E + (size_t)bh * NCH;
    size_t base = ((size_t)bh * NCH) * 8192 + (size_t)e4 * 4;
    for (int c = 0; c < NCH; ++c, base += 8192) {
        *(float4*)(g_stT + base) = S;
        float  E = __ldg(Ep + c);
        float4 g = *(const float4*)(g_G + base);
        S.x = E * S.x + g.x;
        S.y = E * S.y + g.y;
        S.z = E * S.z + g.z;
        S.w = E * S.w + g.w;
    }
}

// ---------------- Y kernel ---------------------------------------------------
// Y(64x64) = M(64x192) @ D(192x64); M stored transposed sM[k][t].
#define SMEM_Y ((192 * 64 + 192 * 64 + 64 * 3) * 4)   // 99072 B

__global__ void __launch_bounds__(256, 2)
y_kernel(float* __restrict__ out) {
    extern __shared__ char dyn[];
    float* sD  = (float*)dyn;               // [192][64]
    float* sM  = sD + 192 * 64;             // [k][t]
    float* sac = sM + 192 * 64;             // [64]
    float* sdA = sac + 64;                  // [64]
    float* sEt = sdA + 64;                  // [64]

    const int bid = blockIdx.x;
    const int c   = bid & 31;
    const int bh  = bid >> 5;
    const int b   = bh >> 5;
    const int h   = bh & 31;
    const int tid = threadIdx.x;

    // stage D: X rows 0..63, S^T rows 64..191 (both contiguous)
    const float* xb = g_xp + ((size_t)bh * Lc + c * QC) * 64;
    for (int idx = tid; idx < 1024; idx += 256)
        cpa16(&sD[idx * 4], xb + idx * 4);
    const float* stb = g_stT + ((size_t)bh * NCH + c) * Nc * Pc;
    for (int idx = tid; idx < 2048; idx += 256)
        cpa16(&sD[64 * 64 + idx * 4], stb + idx * 4);
    asm volatile("cp.async.commit_group;");

    if (tid < 64) {
        sdA[tid] = g_dAs[(size_t)bh * Lc + c * QC + tid];
        float v = g_l[(size_t)bh * Lc + c * QC + tid];
        #pragma unroll
        for (int off = 1; off < 32; off <<= 1) {
            float r = __shfl_up_sync(0xffffffffu, v, off);
            if ((tid & 31) >= off) v += r;
        }
        sac[tid] = v;
    }
    __syncthreads();
    if (tid >= 32 && tid < 64) sac[tid] += sac[31];
    __syncthreads();
    if (tid < 64) sEt[tid] = __expf(sac[tid]);
    __syncthreads();

    // build M transposed, all 256 threads: thread = (t, seg)
    {
        const int t   = tid & 63;
        const int seg = tid >> 6;            // 0..3
        // CB part: rows i in [seg*16, seg*16+16)
        int i_lo = seg * 16;
        if (i_lo <= t) {
            int i1 = (t < i_lo + 15) ? t : (i_lo + 15);
            float w = __expf(sac[t] - sac[i1]);
            const float* cbrow = g_CB + (((size_t)b * NCH + c) * QC + t) * QC;
            for (int i = i1; i >= i_lo; --i) {
                sM[i * 64 + t] = w * __ldg(cbrow + i);
                w *= sdA[i];
            }
        }
        int zlo = (i_lo > t + 1) ? i_lo : (t + 1);
        for (int i = zlo; i < i_lo + 16; ++i) sM[i * 64 + t] = 0.f;

        // C part: rows 64+nn, nn in [seg*32, seg*32+32)
        float Et = sEt[t];
        const float* crow = g_C + ((size_t)b * Lc + c * QC + t) * Nc + seg * 32;
        #pragma unroll 8
        for (int nn = 0; nn < 32; ++nn)
            sM[(64 + seg * 32 + nn) * 64 + t] = Et * __ldg(crow + nn);
    }
    asm volatile("cp.async.wait_group 0;");
    __syncthreads();

    // GEMM: tile 2t x 8c per thread
    const int t0 = (tid >> 3) * 2;
    const int c0 = (tid & 7) * 8;
    uint64_t acc[2][4];
    #pragma unroll
    for (int j = 0; j < 2; ++j)
        #pragma unroll
        for (int q = 0; q < 4; ++q) acc[j][q] = 0;

    for (int k = 0; k < 192; ++k) {
        float2 mv = *(const float2*)&sM[k * 64 + t0];
        ulonglong2 dv0 = *(const ulonglong2*)&sD[k * 64 + c0];
        ulonglong2 dv1 = *(const ulonglong2*)&sD[k * 64 + c0 + 4];
        uint64_t m0 = pk2(mv.x, mv.x);
        uint64_t m1 = pk2(mv.y, mv.y);
        acc[0][0] = f2fma(m0, dv0.x, acc[0][0]);
        acc[0][1] = f2fma(m0, dv0.y, acc[0][1]);
        acc[0][2] = f2fma(m0, dv1.x, acc[0][2]);
        acc[0][3] = f2fma(m0, dv1.y, acc[0][3]);
        acc[1][0] = f2fma(m1, dv0.x, acc[1][0]);
        acc[1][1] = f2fma(m1, dv0.y, acc[1][1]);
        acc[1][2] = f2fma(m1, dv1.x, acc[1][2]);
        acc[1][3] = f2fma(m1, dv1.y, acc[1][3]);
    }

    // epilogue: (y + Dh*x) * gate ; 8 p's lie within one 16-p plane
    const int q4 = c0 >> 4;          // plane
    const int pi = c0 & 15;          // pair index within plane
    #pragma unroll
    for (int tt = 0; tt < 2; ++tt) {
        int tg = c * QC + t0 + tt;
        const float4* gdp = (const float4*)(g_gd +
            (((size_t)(bh * 4 + q4)) * Lc + tg) * 32 + pi * 2);
        float4 gd0 = __ldg(gdp);
        float4 gd1 = __ldg(gdp + 1);
        float4 gd2 = __ldg(gdp + 2);
        float4 gd3 = __ldg(gdp + 3);
        float y0, y1, y2, y3, y4, y5, y6, y7;
        unpk2(acc[tt][0], y0, y1);
        unpk2(acc[tt][1], y2, y3);
        unpk2(acc[tt][2], y4, y5);
        unpk2(acc[tt][3], y6, y7);
        float4 o0, o1;
        o0.x = (y0 + gd0.y) * gd0.x;
        o0.y = (y1 + gd0.w) * gd0.z;
        o0.z = (y2 + gd1.y) * gd1.x;
        o0.w = (y3 + gd1.w) * gd1.z;
        o1.x = (y4 + gd2.y) * gd2.x;
        o1.y = (y5 + gd2.w) * gd2.z;
        o1.z = (y6 + gd3.y) * gd3.x;
        o1.w = (y7 + gd3.w) * gd3.z;
        float* op = out + ((size_t)b * Lc + tg) * DINNER + h * 64 + c0;
        *(float4*)op       = o0;
        *(float4*)(op + 4) = o1;
    }
}

// ---------------- launch -----------------------------------------------------
extern "C" void kernel_launch(void* const* d_in, const int* in_sizes, int n_in,
                              void* d_out, int out_size) {
    const float* zxbcdt     = (const float*)d_in[0];
    const float* conv_w     = (const float*)d_in[1];
    const float* conv_b     = (const float*)d_in[2];
    const float* dt_bias    = (const float*)d_in[3];
    const float* a_log      = (const float*)d_in[4];
    const float* d_param    = (const float*)d_in[5];
    const float* dt_scale   = (const float*)d_in[6];
    const float* init_state = (const float*)d_in[7];
    float* out = (float*)d_out;

    cudaFuncSetAttribute(g_kernel, cudaFuncAttributeMaxDynamicSharedMemorySize, SMEM_G);
    cudaFuncSetAttribute(y_kernel, cudaFuncAttributeMaxDynamicSharedMemorySize, SMEM_Y);

    dim3 pg(Bc * Lc, (DCONVC + Hc + 255) / 256);
    prepass_kernel<<<pg, 256>>>(zxbcdt, conv_w, conv_b, dt_bias, a_log, d_param, dt_scale);
    cb_kernel<<<Bc * NCH, 256>>>();
    g_kernel<<<Bc * Hc * NCH, 256, SMEM_G>>>();
    chain_kernel<<<Bc * Hc * 8, 256>>>(init_state);
    y_kernel<<<Bc * Hc * NCH, 256, SMEM_Y>>>(out);
}

// round 16
// speedup vs baseline: 1.4252x; 1.4252x over previous
#include <cuda_runtime.h>
#include <cstdint>

// Problem constants
#define Lc     2048
#define Bc     2
#define Hc     32
#define Pc     64
#define Nc     128
#define DPROJ  4384
#define DCONVC 2304
#define DINNER 2048
#define QC     64            // chunk size
#define NCH    (Lc / QC)     // 32 chunks

// ---------------- scratch (static device globals) ---------------------------
__device__ __align__(16) float g_xp [(size_t)Bc * Hc * Lc * 64];       // x~ [bh][t][64]
__device__ __align__(16) float g_gd [(size_t)Bc * Hc * 4 * Lc * 32];   // (gate,Dx) pairs
__device__ __align__(16) float g_B  [(size_t)Bc * Lc * Nc];
__device__ __align__(16) float g_C  [(size_t)Bc * Lc * Nc];
__device__ __align__(16) float g_l  [(size_t)Bc * Hc * Lc];            // l = dt*A
__device__ __align__(16) float g_dAs[(size_t)Bc * Hc * Lc];            // dA scalar
__device__ __align__(16) float g_CB [(size_t)Bc * NCH * QC * QC];      // [b][c][t][i]
__device__ __align__(16) float g_G  [(size_t)Bc * Hc * NCH * Nc * Pc]; // [bhc][n][p]
__device__ __align__(16) float g_stT[(size_t)Bc * Hc * NCH * Nc * Pc]; // [bhc][n][p]
__device__ __align__(16) float g_E  [(size_t)Bc * Hc * NCH];           // chunk decay

// ---------------- helpers ----------------------------------------------------
__device__ __forceinline__ uint64_t pk2(float lo, float hi) {
    uint64_t r; asm("mov.b64 %0, {%1,%2};" : "=l"(r) : "f"(lo), "f"(hi)); return r;
}
__device__ __forceinline__ void unpk2(uint64_t v, float& lo, float& hi) {
    asm("mov.b64 {%0,%1}, %2;" : "=f"(lo), "=f"(hi) : "l"(v));
}
__device__ __forceinline__ uint64_t f2fma(uint64_t a, uint64_t b, uint64_t c) {
    uint64_t d; asm("fma.rn.f32x2 %0, %1, %2, %3;" : "=l"(d) : "l"(a), "l"(b), "l"(c)); return d;
}
__device__ __forceinline__ void cpa16(void* sm, const void* gm) {
    unsigned sa = (unsigned)__cvta_generic_to_shared(sm);
    asm volatile("cp.async.cg.shared.global [%0], [%1], 16;" :: "r"(sa), "l"(gm));
}
__device__ __forceinline__ float fast_silu(float v) {
    return v * (1.f / (1.f + __expf(-v)));
}

// ---------------- pre-pass ---------------------------------------------------
__global__ void prepass_kernel(const float* __restrict__ zx,
                               const float* __restrict__ cw,
                               const float* __restrict__ cb,
                               const float* __restrict__ dt_bias,
                               const float* __restrict__ a_log,
                               const float* __restrict__ d_param,
                               const float* __restrict__ dt_scale) {
    int bt  = blockIdx.x;            // b*L + t
    int b   = bt >> 11;
    int t   = bt & (Lc - 1);
    int idx = blockIdx.y * 256 + threadIdx.x;
    if (idx >= DCONVC + Hc) return;

    if (idx < DCONVC) {
        int cc = idx;
        int col = DINNER + cc;
        float acc = cb[cc];
        const float* w = cw + cc * 4;
        #pragma unroll
        for (int i = 0; i < 4; ++i) {
            int l2 = t - 3 + i;
            if (l2 >= 0) acc += w[i] * zx[((size_t)(b * Lc + l2)) * DPROJ + col];
        }
        float v = fast_silu(acc);
        if (cc < DINNER) {
            int h = cc >> 6, p = cc & 63;
            float draw = zx[(size_t)bt * DPROJ + (DPROJ - Hc) + h] * dt_scale[h] + dt_bias[h];
            float dt = (draw > 20.f) ? draw : log1pf(expf(draw));
            dt = fminf(fmaxf(dt, 0.f), 100.f);
            float xt = dt * v;                       // x~ = dt * x
            g_xp[((size_t)(b * Hc + h) * Lc + t) * 64 + p] = xt;
            float z = zx[(size_t)bt * DPROJ + cc];
            size_t o = ((((size_t)(b * Hc + h) * 4 + (p >> 4)) * Lc + t) * 32 + (p & 15) * 2);
            g_gd[o]     = fast_silu(z);              // gate
            g_gd[o + 1] = d_param[h] * v;            // Dh * x
        } else if (cc < DINNER + Nc) {
            g_B[((size_t)(b * Lc + t)) * Nc + (cc - DINNER)] = v;
        } else {
            g_C[((size_t)(b * Lc + t)) * Nc + (cc - DINNER - Nc)] = v;
        }
    } else {
        int h = idx - DCONVC;
        float draw = zx[(size_t)bt * DPROJ + (DPROJ - Hc) + h] * dt_scale[h] + dt_bias[h];
        float dt = (draw > 20.f) ? draw : log1pf(expf(draw));
        dt = fminf(fmaxf(dt, 0.f), 100.f);
        float A  = -expf(a_log[h]);
        float l  = dt * A;
        g_l  [(size_t)(b * Hc + h) * Lc + t] = l;
        g_dAs[(size_t)(b * Hc + h) * Lc + t] = expf(l);
    }
}

// ---------------- CB kernel: CB[t][i] = C_t . B_i per (b,chunk) --------------
__global__ void __launch_bounds__(256)
cb_kernel() {
    const int bc = blockIdx.x;          // b*NCH + c
    const int b  = bc >> 5;
    const int c  = bc & 31;
    const int tid = threadIdx.x;

    __shared__ float sB[QC * 132];

    for (int idx = tid; idx < QC * 32; idx += 256) {
        int row = idx >> 5, sg = idx & 31;
        cpa16(&sB[row * 132 + sg * 4],
              g_B + ((size_t)b * Lc + c * QC + row) * Nc + sg * 4);
    }
    asm volatile("cp.async.commit_group;");
    asm volatile("cp.async.wait_group 0;");
    __syncthreads();

    const int t  = tid >> 2;
    const int ig = tid & 3;
    const float4* c4p = (const float4*)(g_C + ((size_t)b * Lc + c * QC + t) * Nc);
    float acc[16];
    #pragma unroll
    for (int j = 0; j < 16; ++j) acc[j] = 0.f;

    for (int nq = 0; nq < 32; ++nq) {
        float4 cv = __ldg(c4p + nq);
        #pragma unroll
        for (int j = 0; j < 16; ++j) {
            float4 bv = *(const float4*)&sB[(ig * 16 + j) * 132 + nq * 4];
            acc[j] += cv.x * bv.x + cv.y * bv.y + cv.z * bv.z + cv.w * bv.w;
        }
    }
    float* dst = g_CB + ((size_t)bc * QC + t) * QC + ig * 16;
    #pragma unroll
    for (int j = 0; j < 16; ++j) dst[j] = acc[j];
}

// ---------------- G kernel: G_c[n][p] = sum_i w_i * x~_i[p] * B_i[n] ---------
// Conflict-free tiling: 8n x 4p per thread (16 lanes cover a contiguous row).
#define SMEM_G ((64 * 64 + 64 * 128 + 64 + 64) * 4)   // 49664 B

__global__ void __launch_bounds__(256, 2)
g_kernel() {
    extern __shared__ char dyng[];
    float* sX  = (float*)dyng;              // [i][p] 64x64
    float* sWB = sX + 64 * 64;              // [i][n] 64x128
    float* sac = sWB + 64 * 128;            // [64]
    float* sw  = sac + 64;                  // [64]

    const int bid = blockIdx.x;             // bh*NCH + c
    const int c   = bid & 31;
    const int bh  = bid >> 5;
    const int b   = bh >> 5;
    const int tid = threadIdx.x;

    const float* xbase = g_xp + ((size_t)bh * Lc + c * QC) * 64;
    for (int idx = tid; idx < 1024; idx += 256)
        cpa16(&sX[idx * 4], xbase + idx * 4);
    const float* bbase = g_B + ((size_t)b * Lc + c * QC) * Nc;
    for (int idx = tid; idx < 2048; idx += 256)
        cpa16(&sWB[idx * 4], bbase + idx * 4);
    asm volatile("cp.async.commit_group;");

    if (tid < 64) {
        float v = g_l[(size_t)bh * Lc + c * QC + tid];
        #pragma unroll
        for (int off = 1; off < 32; off <<= 1) {
            float r = __shfl_up_sync(0xffffffffu, v, off);
            if ((tid & 31) >= off) v += r;
        }
        sac[tid] = v;
    }
    __syncthreads();
    if (tid >= 32 && tid < 64) sac[tid] += sac[31];
    __syncthreads();
    float actot = sac[63];
    if (tid < 64) sw[tid] = __expf(actot - sac[tid]);
    if (tid == 0) g_E[(size_t)bh * NCH + c] = __expf(actot);
    asm volatile("cp.async.wait_group 0;");
    __syncthreads();

    // scale B rows by suffix decay w
    for (int idx = tid; idx < 2048; idx += 256) {
        int i = idx >> 5;
        float4* pp = (float4*)&sWB[idx * 4];
        float4 v = *pp;
        float w = sw[i];
        v.x *= w; v.y *= w; v.z *= w; v.w *= w;
        *pp = v;
    }
    __syncthreads();

    // GEMM: out rows = n (128), cols = p (64); tile 8n x 4p per thread
    const int n0 = (tid >> 4) * 8;
    const int p0 = (tid & 15) * 4;
    uint64_t acc[8][2];
    #pragma unroll
    for (int j = 0; j < 8; ++j) { acc[j][0] = 0; acc[j][1] = 0; }

    for (int i = 0; i < 64; ++i) {
        ulonglong2 xv = *(const ulonglong2*)&sX[i * 64 + p0];   // 4 p as 2 f2
        float wb[8];
        *(float4*)&wb[0] = *(const float4*)&sWB[i * 128 + n0];
        *(float4*)&wb[4] = *(const float4*)&sWB[i * 128 + n0 + 4];
        #pragma unroll
        for (int j = 0; j < 8; ++j) {
            uint64_t m2 = pk2(wb[j], wb[j]);
            acc[j][0] = f2fma(m2, xv.x, acc[j][0]);
            acc[j][1] = f2fma(m2, xv.y, acc[j][1]);
        }
    }
    #pragma unroll
    for (int j = 0; j < 8; ++j) {
        float* dst = g_G + (((size_t)bid) * Nc + n0 + j) * Pc + p0;
        *(ulonglong2*)dst = *(ulonglong2*)&acc[j][0];
    }
}

// ---------------- chain kernel: elementwise-parallel -------------------------
__global__ void __launch_bounds__(256)
chain_kernel(const float* __restrict__ init_state) {
    const int bh = blockIdx.x >> 3;
    const int sl = blockIdx.x & 7;
    const int e4 = sl * 256 + threadIdx.x;     // float4 index in [0, 2048)
    const int n  = e4 >> 4;
    const int p0 = (e4 & 15) * 4;

    const float* ist = init_state + (size_t)bh * Pc * Nc;
    float4 S;
    S.x = ist[(size_t)(p0 + 0) * Nc + n];
    S.y = ist[(size_t)(p0 + 1) * Nc + n];
    S.z = ist[(size_t)(p0 + 2) * Nc + n];
    S.w = ist[(size_t)(p0 + 3) * Nc + n];

    const float* Ep = g_E + (size_t)bh * NCH;
    size_t base = ((size_t)bh * NCH) * 8192 + (size_t)e4 * 4;
    for (int c = 0; c < NCH; ++c, base += 8192) {
        *(float4*)(g_stT + base) = S;
        float  E = __ldg(Ep + c);
        float4 g = *(const float4*)(g_G + base);
        S.x = E * S.x + g.x;
        S.y = E * S.y + g.y;
        S.z = E * S.z + g.z;
        S.w = E * S.w + g.w;
    }
}

// ---------------- Y kernel ---------------------------------------------------
// Y(64x64) = M(64x192) @ D(192x64); M transposed sM[k][t].
// Conflict-free GEMM tiling: 4t x 4c per thread.  Parallel M-build (256 thr).
#define SMEM_Y ((192 * 64 + 192 * 64 + 64 * 3) * 4)   // 99072 B

__global__ void __launch_bounds__(256, 2)
y_kernel(float* __restrict__ out) {
    extern __shared__ char dyn[];
    float* sD  = (float*)dyn;               // [192][64]
    float* sM  = sD + 192 * 64;             // [k][t]
    float* sac = sM + 192 * 64;             // [64]
    float* sdA = sac + 64;                  // [64]
    float* sEt = sdA + 64;                  // [64]

    const int bid = blockIdx.x;
    const int c   = bid & 31;
    const int bh  = bid >> 5;
    const int b   = bh >> 5;
    const int h   = bh & 31;
    const int tid = threadIdx.x;

    // stage D: X rows 0..63, S^T rows 64..191
    const float* xb = g_xp + ((size_t)bh * Lc + c * QC) * 64;
    for (int idx = tid; idx < 1024; idx += 256)
        cpa16(&sD[idx * 4], xb + idx * 4);
    const float* stb = g_stT + ((size_t)bh * NCH + c) * Nc * Pc;
    for (int idx = tid; idx < 2048; idx += 256)
        cpa16(&sD[64 * 64 + idx * 4], stb + idx * 4);
    asm volatile("cp.async.commit_group;");

    if (tid < 64) {
        sdA[tid] = g_dAs[(size_t)bh * Lc + c * QC + tid];
        float v = g_l[(size_t)bh * Lc + c * QC + tid];
        #pragma unroll
        for (int off = 1; off < 32; off <<= 1) {
            float r = __shfl_up_sync(0xffffffffu, v, off);
            if ((tid & 31) >= off) v += r;
        }
        sac[tid] = v;
    }
    __syncthreads();
    if (tid >= 32 && tid < 64) sac[tid] += sac[31];
    __syncthreads();
    if (tid < 64) sEt[tid] = __expf(sac[tid]);
    __syncthreads();

    // build M transposed, all 256 threads: thread = (t, seg)
    {
        const int t   = tid & 63;
        const int seg = tid >> 6;            // 0..3
        int i_lo = seg * 16;
        if (i_lo <= t) {
            int i1 = (t < i_lo + 15) ? t : (i_lo + 15);
            float w = __expf(sac[t] - sac[i1]);
            const float* cbrow = g_CB + (((size_t)b * NCH + c) * QC + t) * QC;
            for (int i = i1; i >= i_lo; --i) {
                sM[i * 64 + t] = w * __ldg(cbrow + i);
                w *= sdA[i];
            }
        }
        int zlo = (i_lo > t + 1) ? i_lo : (t + 1);
        for (int i = zlo; i < i_lo + 16; ++i) sM[i * 64 + t] = 0.f;

        float Et = sEt[t];
        const float* crow = g_C + ((size_t)b * Lc + c * QC + t) * Nc + seg * 32;
        #pragma unroll 8
        for (int nn = 0; nn < 32; ++nn)
            sM[(64 + seg * 32 + nn) * 64 + t] = Et * __ldg(crow + nn);
    }
    asm volatile("cp.async.wait_group 0;");
    __syncthreads();

    // GEMM: tile 4t x 4c per thread (conflict-free: 16 lanes cover one row)
    const int t0 = (tid >> 4) * 4;
    const int c0 = (tid & 15) * 4;
    uint64_t acc[4][2];
    #pragma unroll
    for (int j = 0; j < 4; ++j) { acc[j][0] = 0; acc[j][1] = 0; }

    for (int k = 0; k < 192; ++k) {
        float mv[4];
        *(float4*)mv = *(const float4*)&sM[k * 64 + t0];
        ulonglong2 dv = *(const ulonglong2*)&sD[k * 64 + c0];
        #pragma unroll
        for (int tt = 0; tt < 4; ++tt) {
            uint64_t m2 = pk2(mv[tt], mv[tt]);
            acc[tt][0] = f2fma(m2, dv.x, acc[tt][0]);
            acc[tt][1] = f2fma(m2, dv.y, acc[tt][1]);
        }
    }

    // epilogue: (y + Dh*x) * gate
    const int q4 = c0 >> 4;
    #pragma unroll
    for (int tt = 0; tt < 4; ++tt) {
        int tg = c * QC + t0 + tt;
        const float4* gdp = (const float4*)(g_gd +
            (((size_t)(bh * 4 + q4)) * Lc + tg) * 32 + (c0 & 15) * 2);
        float4 gd0 = __ldg(gdp);
        float4 gd1 = __ldg(gdp + 1);
        float y0, y1, y2, y3;
        unpk2(acc[tt][0], y0, y1);
        unpk2(acc[tt][1], y2, y3);
        float4 o;
        o.x = (y0 + gd0.y) * gd0.x;
        o.y = (y1 + gd0.w) * gd0.z;
        o.z = (y2 + gd1.y) * gd1.x;
        o.w = (y3 + gd1.w) * gd1.z;
        *(float4*)(out + ((size_t)b * Lc + tg) * DINNER + h * 64 + c0) = o;
    }
}

// ---------------- launch -----------------------------------------------------
extern "C" void kernel_launch(void* const* d_in, const int* in_sizes, int n_in,
                              void* d_out, int out_size) {
    const float* zxbcdt     = (const float*)d_in[0];
    const float* conv_w     = (const float*)d_in[1];
    const float* conv_b     = (const float*)d_in[2];
    const float* dt_bias    = (const float*)d_in[3];
    const float* a_log      = (const float*)d_in[4];
    const float* d_param    = (const float*)d_in[5];
    const float* dt_scale   = (const float*)d_in[6];
    const float* init_state = (const float*)d_in[7];
    float* out = (float*)d_out;

    cudaFuncSetAttribute(g_kernel, cudaFuncAttributeMaxDynamicSharedMemorySize, SMEM_G);
    cudaFuncSetAttribute(y_kernel, cudaFuncAttributeMaxDynamicSharedMemorySize, SMEM_Y);

    dim3 pg(Bc * Lc, (DCONVC + Hc + 255) / 256);
    prepass_kernel<<<pg, 256>>>(zxbcdt, conv_w, conv_b, dt_bias, a_log, d_param, dt_scale);
    cb_kernel<<<Bc * NCH, 256>>>();
    g_kernel<<<Bc * Hc * NCH, 256, SMEM_G>>>();
    chain_kernel<<<Bc * Hc * 8, 256>>>(init_state);
    y_kernel<<<Bc * Hc * NCH, 256, SMEM_Y>>>(out);
}

// round 17
// speedup vs baseline: 1.7469x; 1.2257x over previous
#include <cuda_runtime.h>
#include <cstdint>

// Problem constants
#define Lc     2048
#define Bc     2
#define Hc     32
#define Pc     64
#define Nc     128
#define DPROJ  4384
#define DCONVC 2304
#define DINNER 2048
#define QC     64            // chunk size
#define NCH    (Lc / QC)     // 32 chunks

// ---------------- scratch (static device globals) ---------------------------
__device__ __align__(16) float g_xp [(size_t)Bc * Hc * Lc * 64];       // x~ [bh][t][64]
__device__ __align__(16) float g_gd [(size_t)Bc * Hc * 4 * Lc * 32];   // (gate,Dx) pairs
__device__ __align__(16) float g_B  [(size_t)Bc * Lc * Nc];
__device__ __align__(16) float g_C  [(size_t)Bc * Lc * Nc];            // [b][t][n]
__device__ __align__(16) float g_Ct [(size_t)Bc * Nc * Lc];            // [b][n][t]
__device__ __align__(16) float g_l  [(size_t)Bc * Hc * Lc];            // l = dt*A
__device__ __align__(16) float g_dAs[(size_t)Bc * Hc * Lc];            // dA scalar
__device__ __align__(16) float g_CBt[(size_t)Bc * NCH * QC * QC];      // [b][c][i][t]
__device__ __align__(16) float g_G  [(size_t)Bc * Hc * NCH * Nc * Pc]; // [bhc][n][p]
__device__ __align__(16) float g_stT[(size_t)Bc * Hc * NCH * Nc * Pc]; // [bhc][n][p]
__device__ __align__(16) float g_E  [(size_t)Bc * Hc * NCH];           // chunk decay

// ---------------- helpers ----------------------------------------------------
__device__ __forceinline__ uint64_t pk2(float lo, float hi) {
    uint64_t r; asm("mov.b64 %0, {%1,%2};" : "=l"(r) : "f"(lo), "f"(hi)); return r;
}
__device__ __forceinline__ void unpk2(uint64_t v, float& lo, float& hi) {
    asm("mov.b64 {%0,%1}, %2;" : "=f"(lo), "=f"(hi) : "l"(v));
}
__device__ __forceinline__ uint64_t f2fma(uint64_t a, uint64_t b, uint64_t c) {
    uint64_t d; asm("fma.rn.f32x2 %0, %1, %2, %3;" : "=l"(d) : "l"(a), "l"(b), "l"(c)); return d;
}
__device__ __forceinline__ uint64_t f2mul(uint64_t a, uint64_t b) {
    uint64_t d; asm("mul.rn.f32x2 %0, %1, %2;" : "=l"(d) : "l"(a), "l"(b)); return d;
}
__device__ __forceinline__ void cpa16(void* sm, const void* gm) {
    unsigned sa = (unsigned)__cvta_generic_to_shared(sm);
    asm volatile("cp.async.cg.shared.global [%0], [%1], 16;" :: "r"(sa), "l"(gm));
}
__device__ __forceinline__ float fast_silu(float v) {
    return v * (1.f / (1.f + __expf(-v)));
}

// ---------------- pre-pass ---------------------------------------------------
__global__ void prepass_kernel(const float* __restrict__ zx,
                               const float* __restrict__ cw,
                               const float* __restrict__ cb,
                               const float* __restrict__ dt_bias,
                               const float* __restrict__ a_log,
                               const float* __restrict__ d_param,
                               const float* __restrict__ dt_scale) {
    int bt  = blockIdx.x;            // b*L + t
    int b   = bt >> 11;
    int t   = bt & (Lc - 1);
    int idx = blockIdx.y * 256 + threadIdx.x;
    if (idx >= DCONVC + Hc) return;

    if (idx < DCONVC) {
        int cc = idx;
        int col = DINNER + cc;
        float acc = cb[cc];
        const float* w = cw + cc * 4;
        #pragma unroll
        for (int i = 0; i < 4; ++i) {
            int l2 = t - 3 + i;
            if (l2 >= 0) acc += w[i] * zx[((size_t)(b * Lc + l2)) * DPROJ + col];
        }
        float v = fast_silu(acc);
        if (cc < DINNER) {
            int h = cc >> 6, p = cc & 63;
            float draw = zx[(size_t)bt * DPROJ + (DPROJ - Hc) + h] * dt_scale[h] + dt_bias[h];
            float dt = (draw > 20.f) ? draw : __logf(1.f + __expf(draw));
            dt = fminf(fmaxf(dt, 0.f), 100.f);
            float xt = dt * v;                       // x~ = dt * x
            g_xp[((size_t)(b * Hc + h) * Lc + t) * 64 + p] = xt;
            float z = zx[(size_t)bt * DPROJ + cc];
            size_t o = ((((size_t)(b * Hc + h) * 4 + (p >> 4)) * Lc + t) * 32 + (p & 15) * 2);
            g_gd[o]     = fast_silu(z);              // gate
            g_gd[o + 1] = d_param[h] * v;            // Dh * x
        } else if (cc < DINNER + Nc) {
            g_B[((size_t)(b * Lc + t)) * Nc + (cc - DINNER)] = v;
        } else {
            int n = cc - DINNER - Nc;
            g_C [((size_t)(b * Lc + t)) * Nc + n] = v;
            g_Ct[((size_t)(b * Nc + n)) * Lc + t] = v;
        }
    } else {
        int h = idx - DCONVC;
        float draw = zx[(size_t)bt * DPROJ + (DPROJ - Hc) + h] * dt_scale[h] + dt_bias[h];
        float dt = (draw > 20.f) ? draw : __logf(1.f + __expf(draw));
        dt = fminf(fmaxf(dt, 0.f), 100.f);
        float A  = -expf(a_log[h]);
        float l  = dt * A;
        g_l  [(size_t)(b * Hc + h) * Lc + t] = l;
        g_dAs[(size_t)(b * Hc + h) * Lc + t] = __expf(l);
    }
}

// ---------------- CB kernel: CBt[i][t] = C_t . B_i per (b,chunk) -------------
__global__ void __launch_bounds__(256)
cb_kernel() {
    const int bc = blockIdx.x;          // b*NCH + c
    const int b  = bc >> 5;
    const int c  = bc & 31;
    const int tid = threadIdx.x;

    __shared__ float sB[QC * 132];

    for (int idx = tid; idx < QC * 32; idx += 256) {
        int row = idx >> 5, sg = idx & 31;
        cpa16(&sB[row * 132 + sg * 4],
              g_B + ((size_t)b * Lc + c * QC + row) * Nc + sg * 4);
    }
    asm volatile("cp.async.commit_group;");
    asm volatile("cp.async.wait_group 0;");
    __syncthreads();

    const int t  = tid >> 2;
    const int ig = tid & 3;
    const float4* c4p = (const float4*)(g_C + ((size_t)b * Lc + c * QC + t) * Nc);
    float acc[16];
    #pragma unroll
    for (int j = 0; j < 16; ++j) acc[j] = 0.f;

    for (int nq = 0; nq < 32; ++nq) {
        float4 cv = __ldg(c4p + nq);
        #pragma unroll
        for (int j = 0; j < 16; ++j) {
            float4 bv = *(const float4*)&sB[(ig * 16 + j) * 132 + nq * 4];
            acc[j] += cv.x * bv.x + cv.y * bv.y + cv.z * bv.z + cv.w * bv.w;
        }
    }
    // transposed store: [i][t]
    float* dst = g_CBt + ((size_t)bc * QC) * QC + t;
    #pragma unroll
    for (int j = 0; j < 16; ++j)
        dst[(size_t)(ig * 16 + j) * QC] = acc[j];
}

// ---------------- G kernel: G_c[n][p] = sum_i w_i * x~_i[p] * B_i[n] ---------
#define SMEM_G ((64 * 64 + 64 * 128 + 64 + 64) * 4)   // 49664 B

__global__ void __launch_bounds__(256, 2)
g_kernel() {
    extern __shared__ char dyng[];
    float* sX  = (float*)dyng;              // [i][p] 64x64
    float* sWB = sX + 64 * 64;              // [i][n] 64x128
    float* sac = sWB + 64 * 128;            // [64]
    float* sw  = sac + 64;                  // [64]

    const int bid = blockIdx.x;             // bh*NCH + c
    const int c   = bid & 31;
    const int bh  = bid >> 5;
    const int b   = bh >> 5;
    const int tid = threadIdx.x;

    const float* xbase = g_xp + ((size_t)bh * Lc + c * QC) * 64;
    for (int idx = tid; idx < 1024; idx += 256)
        cpa16(&sX[idx * 4], xbase + idx * 4);
    const float* bbase = g_B + ((size_t)b * Lc + c * QC) * Nc;
    for (int idx = tid; idx < 2048; idx += 256)
        cpa16(&sWB[idx * 4], bbase + idx * 4);
    asm volatile("cp.async.commit_group;");

    if (tid < 64) {
        float v = g_l[(size_t)bh * Lc + c * QC + tid];
        #pragma unroll
        for (int off = 1; off < 32; off <<= 1) {
            float r = __shfl_up_sync(0xffffffffu, v, off);
            if ((tid & 31) >= off) v += r;
        }
        sac[tid] = v;
    }
    __syncthreads();
    if (tid >= 32 && tid < 64) sac[tid] += sac[31];
    __syncthreads();
    float actot = sac[63];
    if (tid < 64) sw[tid] = __expf(actot - sac[tid]);
    if (tid == 0) g_E[(size_t)bh * NCH + c] = __expf(actot);
    asm volatile("cp.async.wait_group 0;");
    __syncthreads();

    for (int idx = tid; idx < 2048; idx += 256) {
        int i = idx >> 5;
        float4* pp = (float4*)&sWB[idx * 4];
        float4 v = *pp;
        float w = sw[i];
        v.x *= w; v.y *= w; v.z *= w; v.w *= w;
        *pp = v;
    }
    __syncthreads();

    const int n0 = (tid >> 4) * 8;
    const int p0 = (tid & 15) * 4;
    uint64_t acc[8][2];
    #pragma unroll
    for (int j = 0; j < 8; ++j) { acc[j][0] = 0; acc[j][1] = 0; }

    for (int i = 0; i < 64; ++i) {
        ulonglong2 xv = *(const ulonglong2*)&sX[i * 64 + p0];
        float wb[8];
        *(float4*)&wb[0] = *(const float4*)&sWB[i * 128 + n0];
        *(float4*)&wb[4] = *(const float4*)&sWB[i * 128 + n0 + 4];
        #pragma unroll
        for (int j = 0; j < 8; ++j) {
            uint64_t m2 = pk2(wb[j], wb[j]);
            acc[j][0] = f2fma(m2, xv.x, acc[j][0]);
            acc[j][1] = f2fma(m2, xv.y, acc[j][1]);
        }
    }
    #pragma unroll
    for (int j = 0; j < 8; ++j) {
        float* dst = g_G + (((size_t)bid) * Nc + n0 + j) * Pc + p0;
        *(ulonglong2*)dst = *(ulonglong2*)&acc[j][0];
    }
}

// ---------------- chain kernel: elementwise-parallel -------------------------
__global__ void __launch_bounds__(256)
chain_kernel(const float* __restrict__ init_state) {
    const int bh = blockIdx.x >> 3;
    const int sl = blockIdx.x & 7;
    const int e4 = sl * 256 + threadIdx.x;
    const int n  = e4 >> 4;
    const int p0 = (e4 & 15) * 4;

    const float* ist = init_state + (size_t)bh * Pc * Nc;
    float4 S;
    S.x = ist[(size_t)(p0 + 0) * Nc + n];
    S.y = ist[(size_t)(p0 + 1) * Nc + n];
    S.z = ist[(size_t)(p0 + 2) * Nc + n];
    S.w = ist[(size_t)(p0 + 3) * Nc + n];

    const float* Ep = g_E + (size_t)bh * NCH;
    size_t base = ((size_t)bh * NCH) * 8192 + (size_t)e4 * 4;
    for (int c = 0; c < NCH; ++c, base += 8192) {
        *(float4*)(g_stT + base) = S;
        float  E = __ldg(Ep + c);
        float4 g = *(const float4*)(g_G + base);
        S.x = E * S.x + g.x;
        S.y = E * S.y + g.y;
        S.z = E * S.z + g.z;
        S.w = E * S.w + g.w;
    }
}

// ---------------- Y kernel ---------------------------------------------------
// Y = decayCB(64x64)@X(64x64) + diag(Et)*(C(64x128)@S^T(128x64))
// sM[k][t]: rows 0..63 = decay*CB (built, coalesced CBt reads);
//           rows 64..191 = raw C (cp.async from g_Ct).  GEMM two-phase.
#define SMEM_Y ((192 * 64 + 192 * 64 + 64 * 3) * 4)   // 99072 B

__global__ void __launch_bounds__(256, 2)
y_kernel(float* __restrict__ out) {
    extern __shared__ char dyn[];
    float* sD  = (float*)dyn;               // [192][64]
    float* sM  = sD + 192 * 64;             // [k][t]
    float* sac = sM + 192 * 64;             // [64]
    float* sdA = sac + 64;                  // [64]
    float* sEt = sdA + 64;                  // [64]

    const int bid = blockIdx.x;
    const int c   = bid & 31;
    const int bh  = bid >> 5;
    const int b   = bh >> 5;
    const int h   = bh & 31;
    const int tid = threadIdx.x;

    // stage D: X rows 0..63, S^T rows 64..191
    const float* xb = g_xp + ((size_t)bh * Lc + c * QC) * 64;
    for (int idx = tid; idx < 1024; idx += 256)
        cpa16(&sD[idx * 4], xb + idx * 4);
    const float* stb = g_stT + ((size_t)bh * NCH + c) * Nc * Pc;
    for (int idx = tid; idx < 2048; idx += 256)
        cpa16(&sD[64 * 64 + idx * 4], stb + idx * 4);
    // stage M rows 64..191 = C^T slices (contiguous in g_Ct)
    for (int idx = tid; idx < 2048; idx += 256) {
        int n = idx >> 4, sg = idx & 15;
        cpa16(&sM[(64 + n) * 64 + sg * 4],
              g_Ct + ((size_t)b * Nc + n) * Lc + c * QC + sg * 4);
    }
    asm volatile("cp.async.commit_group;");

    if (tid < 64) {
        sdA[tid] = g_dAs[(size_t)bh * Lc + c * QC + tid];
        float v = g_l[(size_t)bh * Lc + c * QC + tid];
        #pragma unroll
        for (int off = 1; off < 32; off <<= 1) {
            float r = __shfl_up_sync(0xffffffffu, v, off);
            if ((tid & 31) >= off) v += r;
        }
        sac[tid] = v;
    }
    __syncthreads();
    if (tid >= 32 && tid < 64) sac[tid] += sac[31];
    __syncthreads();
    if (tid < 64) sEt[tid] = __expf(sac[tid]);
    __syncthreads();

    // build M rows 0..63 (decay * CBt), coalesced reads: lane == t
    {
        const int t   = tid & 63;
        const int seg = tid >> 6;            // 0..3
        int i_lo = seg * 16;
        const float* cbt = g_CBt + ((size_t)(b * NCH + c) * QC) * QC + t;
        if (i_lo <= t) {
            int i1 = (t < i_lo + 15) ? t : (i_lo + 15);
            float w = __expf(sac[t] - sac[i1]);
            for (int i = i1; i >= i_lo; --i) {
                sM[i * 64 + t] = w * __ldg(cbt + (size_t)i * QC);
                w *= sdA[i];
            }
        }
        int zlo = (i_lo > t + 1) ? i_lo : (t + 1);
        for (int i = zlo; i < i_lo + 16; ++i) sM[i * 64 + t] = 0.f;
    }
    asm volatile("cp.async.wait_group 0;");
    __syncthreads();

    // GEMM: tile 4t x 4c; phase 1 = C @ S^T (k 64..191), scale by Et, then CB @ X
    const int t0 = (tid >> 4) * 4;
    const int c0 = (tid & 15) * 4;
    uint64_t acc[4][2];
    #pragma unroll
    for (int j = 0; j < 4; ++j) { acc[j][0] = 0; acc[j][1] = 0; }

    for (int k = 64; k < 192; ++k) {
        float mv[4];
        *(float4*)mv = *(const float4*)&sM[k * 64 + t0];
        ulonglong2 dv = *(const ulonglong2*)&sD[k * 64 + c0];
        #pragma unroll
        for (int tt = 0; tt < 4; ++tt) {
            uint64_t m2 = pk2(mv[tt], mv[tt]);
            acc[tt][0] = f2fma(m2, dv.x, acc[tt][0]);
            acc[tt][1] = f2fma(m2, dv.y, acc[tt][1]);
        }
    }
    {
        float et[4];
        *(float4*)et = *(const float4*)&sEt[t0];
        #pragma unroll
        for (int tt = 0; tt < 4; ++tt) {
            uint64_t e2 = pk2(et[tt], et[tt]);
            acc[tt][0] = f2mul(acc[tt][0], e2);
            acc[tt][1] = f2mul(acc[tt][1], e2);
        }
    }
    for (int k = 0; k < 64; ++k) {
        float mv[4];
        *(float4*)mv = *(const float4*)&sM[k * 64 + t0];
        ulonglong2 dv = *(const ulonglong2*)&sD[k * 64 + c0];
        #pragma unroll
        for (int tt = 0; tt < 4; ++tt) {
            uint64_t m2 = pk2(mv[tt], mv[tt]);
            acc[tt][0] = f2fma(m2, dv.x, acc[tt][0]);
            acc[tt][1] = f2fma(m2, dv.y, acc[tt][1]);
        }
    }

    // epilogue: (y + Dh*x) * gate
    const int q4 = c0 >> 4;
    #pragma unroll
    for (int tt = 0; tt < 4; ++tt) {
        int tg = c * QC + t0 + tt;
        const float4* gdp = (const float4*)(g_gd +
            (((size_t)(bh * 4 + q4)) * Lc + tg) * 32 + (c0 & 15) * 2);
        float4 gd0 = __ldg(gdp);
        float4 gd1 = __ldg(gdp + 1);
        float y0, y1, y2, y3;
        unpk2(acc[tt][0], y0, y1);
        unpk2(acc[tt][1], y2, y3);
        float4 o;
        o.x = (y0 + gd0.y) * gd0.x;
        o.y = (y1 + gd0.w) * gd0.z;
        o.z = (y2 + gd1.y) * gd1.x;
        o.w = (y3 + gd1.w) * gd1.z;
        *(float4*)(out + ((size_t)b * Lc + tg) * DINNER + h * 64 + c0) = o;
    }
}

// ---------------- launch -----------------------------------------------------
extern "C" void kernel_launch(void* const* d_in, const int* in_sizes, int n_in,
                              void* d_out, int out_size) {
    const float* zxbcdt     = (const float*)d_in[0];
    const float* conv_w     = (const float*)d_in[1];
    const float* conv_b     = (const float*)d_in[2];
    const float* dt_bias    = (const float*)d_in[3];
    const float* a_log      = (const float*)d_in[4];
    const float* d_param    = (const float*)d_in[5];
    const float* dt_scale   = (const float*)d_in[6];
    const float* init_state = (const float*)d_in[7];
    float* out = (float*)d_out;

    cudaFuncSetAttribute(g_kernel, cudaFuncAttributeMaxDynamicSharedMemorySize, SMEM_G);
    cudaFuncSetAttribute(y_kernel, cudaFuncAttributeMaxDynamicSharedMemorySize, SMEM_Y);

    dim3 pg(Bc * Lc, (DCONVC + Hc + 255) / 256);
    prepass_kernel<<<pg, 256>>>(zxbcdt, conv_w, conv_b, dt_bias, a_log, d_param, dt_scale);
    cb_kernel<<<Bc * NCH, 256>>>();
    g_kernel<<<Bc * Hc * NCH, 256, SMEM_G>>>();
    chain_kernel<<<Bc * Hc * 8, 256>>>(init_state);
    y_kernel<<<Bc * Hc * NCH, 256, SMEM_Y>>>(out);
}